// round 7
// baseline (speedup 1.0000x reference)
#include <cuda_runtime.h>
#include <math.h>

#define NB   2
#define NPTS 8192
#define KNN  20
#define GDIM 32
#define G3   (GDIM*GDIM*GDIM)

// ---------------- device scratch (no allocation allowed) ----------------
__device__ int    g_knn[NB * NPTS * KNN];
__device__ float  g_S1[128], g_S2[128], g_SN[64];
__device__ float  g_base1[NB][128];
__device__ float  g_baseN[NB][64];
// grid structures
__device__ float4 g_pts4[NB * NPTS];          // cell-sorted (x,y,z, bits(orig id))
__device__ int    g_cellstart[NB * (G3 + 1)]; // CSR starts per batch
__device__ int    g_cnt[NB * G3];             // counts, then scatter cursors
__device__ float  g_lo[NB][3];
__device__ float  g_invs[NB][3];
__device__ float  g_smin[NB];

// exact-ish gelu (tanh via exp) for the tiny setup MLP
__device__ __forceinline__ float gelu_f(float x) {
    float y = 0.7978845608028654f * (x + 0.044715f * x * x * x);
    float e = __expf(2.0f * y);
    float th = 1.0f - 2.0f / (e + 1.0f);
    return 0.5f * x * (1.0f + th);
}

// fast gelu: tanh.approx.f32
__device__ __forceinline__ float gelu_fast(float x) {
    float y = 0.7978845608028654f * fmaf(0.044715f * x * x, x, x);
    float t;
    asm("tanh.approx.f32 %0, %1;" : "=f"(t) : "f"(y));
    return 0.5f * x * (1.0f + t);
}

__device__ __forceinline__ int cell_of(float v, float lo, float inv) {
    int i = (int)((v - lo) * inv);          // (v-lo) >= 0, trunc == floor
    return i < 0 ? 0 : (i > GDIM - 1 ? GDIM - 1 : i);
}

// ---------------- grid kernel 1: zero counts + bbox (one block per batch) ----------------
__global__ __launch_bounds__(256) void grid_bbox_kernel(const float* __restrict__ z)
{
    const int b   = blockIdx.x;
    const int tid = threadIdx.x;
    const unsigned FULL = 0xffffffffu;

    for (int i = tid; i < G3; i += 256) g_cnt[b * G3 + i] = 0;

    float lx = 1e30f, ly = 1e30f, lz = 1e30f;
    float hx = -1e30f, hy = -1e30f, hz = -1e30f;
    const float* zb = z + (size_t)b * NPTS * 7;
    for (int n = tid; n < NPTS; n += 256) {
        const float* p = zb + (size_t)n * 7;
        float x = p[0], y = p[1], w = p[2];
        lx = fminf(lx, x); hx = fmaxf(hx, x);
        ly = fminf(ly, y); hy = fmaxf(hy, y);
        lz = fminf(lz, w); hz = fmaxf(hz, w);
    }
#pragma unroll
    for (int off = 16; off > 0; off >>= 1) {
        lx = fminf(lx, __shfl_xor_sync(FULL, lx, off));
        ly = fminf(ly, __shfl_xor_sync(FULL, ly, off));
        lz = fminf(lz, __shfl_xor_sync(FULL, lz, off));
        hx = fmaxf(hx, __shfl_xor_sync(FULL, hx, off));
        hy = fmaxf(hy, __shfl_xor_sync(FULL, hy, off));
        hz = fmaxf(hz, __shfl_xor_sync(FULL, hz, off));
    }
    __shared__ float slo[8][3], shi[8][3];
    const int warp = tid >> 5;
    if ((tid & 31) == 0) {
        slo[warp][0] = lx; slo[warp][1] = ly; slo[warp][2] = lz;
        shi[warp][0] = hx; shi[warp][1] = hy; shi[warp][2] = hz;
    }
    __syncthreads();
    if (tid == 0) {
        for (int w2 = 1; w2 < 8; w2++) {
            slo[0][0] = fminf(slo[0][0], slo[w2][0]);
            slo[0][1] = fminf(slo[0][1], slo[w2][1]);
            slo[0][2] = fminf(slo[0][2], slo[w2][2]);
            shi[0][0] = fmaxf(shi[0][0], shi[w2][0]);
            shi[0][1] = fmaxf(shi[0][1], shi[w2][1]);
            shi[0][2] = fmaxf(shi[0][2], shi[w2][2]);
        }
        float smin = 1e30f;
        for (int d = 0; d < 3; d++) {
            float span = fmaxf(shi[0][d] - slo[0][d], 1e-5f);
            g_lo[b][d]   = slo[0][d];
            g_invs[b][d] = (float)GDIM / span;
            smin = fminf(smin, span / (float)GDIM);
        }
        g_smin[b] = smin;
    }
}

// ---------------- grid kernel 2: count points per cell ----------------
__global__ __launch_bounds__(256) void grid_count_kernel(const float* __restrict__ z)
{
    int i = blockIdx.x * 256 + threadIdx.x;
    int b = i >> 13;
    int n = i & (NPTS - 1);
    const float* p = z + ((size_t)b * NPTS + n) * 7;
    int cx = cell_of(p[0], g_lo[b][0], g_invs[b][0]);
    int cy = cell_of(p[1], g_lo[b][1], g_invs[b][1]);
    int cz = cell_of(p[2], g_lo[b][2], g_invs[b][2]);
    int c = (cx * GDIM + cy) * GDIM + cz;
    atomicAdd(&g_cnt[b * G3 + c], 1);
}

// ---------------- grid kernel 3: exclusive scan (one 1024-thr block per batch) ----------------
__global__ __launch_bounds__(1024) void grid_scan_kernel()
{
    __shared__ int sm[1024];
    const int b = blockIdx.x;
    const int t = threadIdx.x;
    const int base = t * 32;

    int sum = 0;
    for (int k = 0; k < 32; k++) sum += g_cnt[b * G3 + base + k];
    sm[t] = sum;
    __syncthreads();
    for (int off = 1; off < 1024; off <<= 1) {
        int v = (t >= off) ? sm[t - off] : 0;
        __syncthreads();
        sm[t] += v;
        __syncthreads();
    }
    int running = sm[t] - sum;   // exclusive prefix
    for (int k = 0; k < 32; k++) {
        int c = base + k;
        int cc = g_cnt[b * G3 + c];
        g_cellstart[b * (G3 + 1) + c] = running;
        g_cnt[b * G3 + c] = running;   // becomes scatter cursor
        running += cc;
    }
    if (t == 1023) g_cellstart[b * (G3 + 1) + G3] = running;  // == NPTS
}

// ---------------- grid kernel 4: scatter points into cell-sorted order ----------------
__global__ __launch_bounds__(256) void grid_scatter_kernel(const float* __restrict__ z)
{
    int i = blockIdx.x * 256 + threadIdx.x;
    int b = i >> 13;
    int n = i & (NPTS - 1);
    const float* p = z + ((size_t)b * NPTS + n) * 7;
    float x = p[0], y = p[1], w = p[2];
    int cx = cell_of(x, g_lo[b][0], g_invs[b][0]);
    int cy = cell_of(y, g_lo[b][1], g_invs[b][1]);
    int cz = cell_of(w, g_lo[b][2], g_invs[b][2]);
    int c = (cx * GDIM + cy) * GDIM + cz;
    int pos = atomicAdd(&g_cnt[b * G3 + c], 1);
    g_pts4[b * NPTS + pos] = make_float4(x, y, w, __int_as_float(n));
}

// ---------------- grid kernel 5: exact kNN via expanding cell rings ----------------
// one thread per query, queries processed in cell-sorted order (warp locality).
__global__ __launch_bounds__(128) void knn_query_kernel()
{
    int i = blockIdx.x * 128 + threadIdx.x;
    int b = i >> 13;
    int slot = i & (NPTS - 1);

    const float4* pts = g_pts4 + (size_t)b * NPTS;
    const int* cs = g_cellstart + (size_t)b * (G3 + 1);

    float4 q4 = pts[slot];
    const float qx = q4.x, qy = q4.y, qz = q4.z;
    const int n = __float_as_int(q4.w);

    const int cx = cell_of(qx, g_lo[b][0], g_invs[b][0]);
    const int cy = cell_of(qy, g_lo[b][1], g_invs[b][1]);
    const int cz = cell_of(qz, g_lo[b][2], g_invs[b][2]);
    const float smin = g_smin[b];

    float bd[KNN];
    int   bi[KNN];
#pragma unroll
    for (int k = 0; k < KNN; k++) { bd[k] = 1e30f; bi[k] = -1; }

    for (int rho = 0; rho <= 2 * GDIM; rho++) {
        int x0 = max(cx - rho, 0), x1 = min(cx + rho, GDIM - 1);
        int y0 = max(cy - rho, 0), y1 = min(cy + rho, GDIM - 1);
        int z0 = max(cz - rho, 0), z1 = min(cz + rho, GDIM - 1);

        for (int ix = x0; ix <= x1; ix++) {
            bool bx = (ix == cx - rho) || (ix == cx + rho);
            for (int iy = y0; iy <= y1; iy++) {
                bool bxy = bx || (iy == cy - rho) || (iy == cy + rho);
                // interior (x,y): only the two z faces belong to this ring
                int zs, ze, zstep;
                if (bxy) { zs = z0; ze = z1; zstep = 1; }
                else     { zs = cz - rho; ze = cz + rho; zstep = 2 * rho; }
                for (int iz = zs; iz <= ze; iz += (zstep > 0 ? zstep : 1)) {
                    if (iz < 0 || iz > GDIM - 1) continue;
                    int c = (ix * GDIM + iy) * GDIM + iz;
                    int s = cs[c], e = cs[c + 1];
                    for (int j = s; j < e; j++) {
                        float4 t4 = pts[j];
                        float dx = qx - t4.x;
                        float dy = qy - t4.y;
                        float dz = qz - t4.z;
                        float d2 = fmaf(dx, dx, fmaf(dy, dy, dz * dz));
                        if (d2 < bd[KNN - 1]) {
                            int id = __float_as_int(t4.w);
                            if (id != n) {
#pragma unroll
                                for (int k = KNN - 1; k > 0; --k) {
                                    if (bd[k] > d2) {
                                        bool sh = bd[k - 1] > d2;
                                        bd[k] = sh ? bd[k - 1] : d2;
                                        bi[k] = sh ? bi[k - 1] : id;
                                    }
                                }
                                if (bd[0] > d2) { bd[0] = d2; bi[0] = id; }
                            }
                        }
                    }
                }
            }
        }
        // stop: points in rings >= rho+1 have distance >= rho*smin
        float bound = (float)rho * smin;
        if (bd[KNN - 1] <= bound * bound * 0.998f) break;
        // whole grid covered -> done regardless
        if (x0 == 0 && y0 == 0 && z0 == 0 &&
            x1 == GDIM - 1 && y1 == GDIM - 1 && z1 == GDIM - 1) break;
    }

    int* o = g_knn + ((size_t)b * NPTS + n) * KNN;
#pragma unroll
    for (int k = 0; k < KNN; k++) o[k] = bi[k];
}

// ---------------- kernel: cond MLP + folded per-batch vectors ----------------
__global__ __launch_bounds__(256) void setup_kernel(
    const float* __restrict__ t, const float* __restrict__ conditioning,
    const float* __restrict__ Wc1, const float* __restrict__ bc1,
    const float* __restrict__ Wc2, const float* __restrict__ bc2,
    const float* __restrict__ Wc3, const float* __restrict__ bc3,
    const float* __restrict__ We1, const float* __restrict__ be1,
    const float* __restrict__ Wn1, const float* __restrict__ bn1)
{
    const unsigned FULL = 0xffffffffu;
    const int tid  = threadIdx.x;
    const int lane = tid & 31;
    const int warp = tid >> 5;

    if (tid < 128) {
        float s1 = 0.f, s2 = 0.f;
#pragma unroll
        for (int c = 0; c < 36; c++) {
            s1 += We1[c * 128 + tid];
            s2 += We1[(36 + c) * 128 + tid];
        }
        g_S1[tid] = s1;
        g_S2[tid] = s2;
    }
    if (tid < 64) {
        float sn = 0.f;
#pragma unroll
        for (int c = 0; c < 36; c++) sn += Wn1[c * 64 + tid];
        g_SN[tid] = sn;
    }

    __shared__ float sc[36], h1[144], h2[144], cv[40];

    for (int b = 0; b < NB; b++) {
        if (tid < 36) {
            float v;
            if (tid < 16) {
                float f = expf(-logf(10000.0f) * (float)tid / 15.0f);
                v = sinf(t[b] * f);
            } else if (tid < 32) {
                int i = tid - 16;
                float f = expf(-logf(10000.0f) * (float)i / 15.0f);
                v = cosf(t[b] * f);
            } else {
                v = conditioning[b * 4 + (tid - 32)];
            }
            sc[tid] = v;
        }
        __syncthreads();
        if (tid < 144) {
            float a = bc1[tid];
#pragma unroll
            for (int c = 0; c < 36; c++) a = fmaf(sc[c], Wc1[c * 144 + tid], a);
            h1[tid] = gelu_f(a);
        }
        __syncthreads();
        for (int o = 0; o < 18; o++) {
            int j = warp + 8 * o;
            float a = 0.f;
#pragma unroll
            for (int r = 0; r < 5; r++) {
                int c = lane + 32 * r;
                if (c < 144) a = fmaf(h1[c], Wc2[c * 144 + j], a);
            }
#pragma unroll
            for (int off = 16; off > 0; off >>= 1)
                a += __shfl_xor_sync(FULL, a, off);
            if (lane == 0) h2[j] = gelu_f(a + bc2[j]);
        }
        __syncthreads();
        for (int o = 0; o < 5; o++) {
            int j = warp + 8 * o;
            if (j < 36) {
                float a = 0.f;
#pragma unroll
                for (int r = 0; r < 5; r++) {
                    int c = lane + 32 * r;
                    if (c < 144) a = fmaf(h2[c], Wc3[c * 36 + j], a);
                }
#pragma unroll
                for (int off = 16; off > 0; off >>= 1)
                    a += __shfl_xor_sync(FULL, a, off);
                if (lane == 0) cv[j] = a + bc3[j];
            }
        }
        __syncthreads();
        if (tid < 128) {
            float a = be1[tid];
#pragma unroll
            for (int c = 0; c < 36; c++)
                a = fmaf(cv[c], We1[c * 128 + tid] + We1[(36 + c) * 128 + tid], a);
            g_base1[b][tid] = a;
        }
        if (tid < 64) {
            float a = bn1[tid];
#pragma unroll
            for (int c = 0; c < 36; c++) a = fmaf(cv[c], Wn1[c * 64 + tid], a);
            g_baseN[b][tid] = a;
        }
        __syncthreads();
    }
}

// ---------------- kernel: edge MLP + softmax + aggregation + node MLP ----------------
__global__ __launch_bounds__(256) void main_kernel(
    const float* __restrict__ z,
    const float* __restrict__ We1, const float* __restrict__ We2,
    const float* __restrict__ be2,
    const float* __restrict__ Wn1, const float* __restrict__ Wn2,
    const float* __restrict__ bn2,
    const float* __restrict__ alpha, const float* __restrict__ beta,
    float* __restrict__ out)
{
    __shared__ float4 part[8][KNN][17];

    const unsigned FULL = 0xffffffffu;
    const int wlocal = threadIdx.x >> 5;
    const int warp = (blockIdx.x * blockDim.x + threadIdx.x) >> 5;
    const int lane = threadIdx.x & 31;
    const int b = warp >> 13;
    const int n = warp & (NPTS - 1);

    const float* zb = z + (size_t)b * NPTS * 7;
    const float* zt = zb + (size_t)n * 7;
    const float ptx = zt[0], pty = zt[1], ptz = zt[2];
    const float vtx = zt[3], vty = zt[4], vtz = zt[5];
    const float mt  = zt[6];

    float relx = 0.f, rely = 0.f, relz = 0.f;
    float vsx = 0.f, vsy = 0.f, vsz = 0.f;
    float msrc = 0.f, r2 = 0.f, dvv = 0.f, dvr = 0.f, dtr = 0.f;
    if (lane < KNN) {
        int src = g_knn[(size_t)warp * KNN + lane];
        const float* zs = zb + (size_t)src * 7;
        float sx = zs[0], sy = zs[1], sz = zs[2];
        vsx = zs[3]; vsy = zs[4]; vsz = zs[5]; msrc = zs[6];
        relx = sx - ptx; rely = sy - pty; relz = sz - ptz;
        r2  = relx * relx + rely * rely + relz * relz;
        dvv = vsx * vtx + vsy * vty + vsz * vtz;
        dvr = vsx * relx + vsy * rely + vsz * relz;
        dtr = vtx * relx + vty * rely + vtz * relz;
    }

    float s1[4], s2[4], w72[4], w73[4], w74[4], w75[4], b1[4];
    float4 we2[4];
#pragma unroll
    for (int qq = 0; qq < 4; qq++) {
        int j = lane + 32 * qq;
        s1[qq]  = g_S1[j];
        s2[qq]  = g_S2[j];
        w72[qq] = We1[72 * 128 + j];
        w73[qq] = We1[73 * 128 + j];
        w74[qq] = We1[74 * 128 + j];
        w75[qq] = We1[75 * 128 + j];
        b1[qq]  = g_base1[b][j];
        we2[qq] = ((const float4*)We2)[j];
    }

#pragma unroll
    for (int e = 0; e < KNN; e++) {
        float em   = __shfl_sync(FULL, msrc, e);
        float er2  = __shfl_sync(FULL, r2,   e);
        float edvv = __shfl_sync(FULL, dvv,  e);
        float edvr = __shfl_sync(FULL, dvr,  e);
        float edtr = __shfl_sync(FULL, dtr,  e);
        float p0 = 0.f, p1 = 0.f, p2 = 0.f, p3 = 0.f;
#pragma unroll
        for (int qq = 0; qq < 4; qq++) {
            float h = b1[qq];
            h = fmaf(em,   s1[qq],  h);
            h = fmaf(mt,   s2[qq],  h);
            h = fmaf(er2,  w72[qq], h);
            h = fmaf(edvv, w73[qq], h);
            h = fmaf(edvr, w74[qq], h);
            h = fmaf(edtr, w75[qq], h);
            float g = gelu_fast(h);
            p0 = fmaf(g, we2[qq].x, p0);
            p1 = fmaf(g, we2[qq].y, p1);
            p2 = fmaf(g, we2[qq].z, p2);
            p3 = fmaf(g, we2[qq].w, p3);
        }
        p0 += __shfl_xor_sync(FULL, p0, 16);
        p1 += __shfl_xor_sync(FULL, p1, 16);
        p2 += __shfl_xor_sync(FULL, p2, 16);
        p3 += __shfl_xor_sync(FULL, p3, 16);
        if (lane < 16) part[wlocal][e][lane] = make_float4(p0, p1, p2, p3);
    }
    __syncwarp();

    float elog = -1e30f, esmsg = 0.f, ecrel = 0.f, ecvel = 0.f;
    if (lane < KNN) {
        float4 acc = part[wlocal][lane][0];
#pragma unroll
        for (int i = 1; i < 16; i++) {
            float4 p = part[wlocal][lane][i];
            acc.x += p.x; acc.y += p.y; acc.z += p.z; acc.w += p.w;
        }
        elog  = acc.x + be2[0];
        esmsg = acc.y + be2[1];
        ecrel = acc.z + be2[2];
        ecvel = acc.w + be2[3];
    }

    float lg = (lane < KNN) ? elog : -1e30f;
    float mx = lg;
#pragma unroll
    for (int off = 16; off > 0; off >>= 1)
        mx = fmaxf(mx, __shfl_xor_sync(FULL, mx, off));
    float a = (lane < KNN) ? __expf(lg - mx) : 0.f;
    float den = a;
#pragma unroll
    for (int off = 16; off > 0; off >>= 1)
        den += __shfl_xor_sync(FULL, den, off);
    float w = a / den;

    float vmx = w * (ecrel * relx + ecvel * vsx);
    float vmy = w * (ecrel * rely + ecvel * vsy);
    float vmz = w * (ecrel * relz + ecvel * vsz);
    float sg  = w * esmsg;
#pragma unroll
    for (int off = 16; off > 0; off >>= 1) {
        vmx += __shfl_xor_sync(FULL, vmx, off);
        vmy += __shfl_xor_sync(FULL, vmy, off);
        vmz += __shfl_xor_sync(FULL, vmz, off);
        sg  += __shfl_xor_sync(FULL, sg,  off);
    }

    float acc2 = 0.f;
#pragma unroll
    for (int qq = 0; qq < 2; qq++) {
        int j = lane + 32 * qq;
        float h = g_baseN[b][j];
        h = fmaf(mt, g_SN[j], h);
        h = fmaf(sg, Wn1[36 * 64 + j], h);
        acc2 = fmaf(gelu_fast(h), Wn2[j], acc2);
    }
#pragma unroll
    for (int off = 16; off > 0; off >>= 1)
        acc2 += __shfl_xor_sync(FULL, acc2, off);

    if (lane == 0) {
        float sout = acc2 + bn2[0];
        float al = alpha[0], be = beta[0];
        float* o = out + (size_t)warp * 7;
        o[0] = ptx + (ptx + al * vmx);
        o[1] = pty + (pty + al * vmy);
        o[2] = ptz + (ptz + al * vmz);
        o[3] = vtx + be * vmx;
        o[4] = vty + be * vmy;
        o[5] = vtz + be * vmz;
        o[6] = mt + sout;
    }
}

// ---------------- launch ----------------
extern "C" void kernel_launch(void* const* d_in, const int* in_sizes, int n_in,
                              void* d_out, int out_size)
{
    const float* z    = (const float*)d_in[0];
    const float* t    = (const float*)d_in[1];
    const float* cond = (const float*)d_in[2];
    const float* Wc1 = (const float*)d_in[4];
    const float* bc1 = (const float*)d_in[5];
    const float* Wc2 = (const float*)d_in[6];
    const float* bc2 = (const float*)d_in[7];
    const float* Wc3 = (const float*)d_in[8];
    const float* bc3 = (const float*)d_in[9];
    const float* We1 = (const float*)d_in[10];
    const float* be1 = (const float*)d_in[11];
    const float* We2 = (const float*)d_in[12];
    const float* be2 = (const float*)d_in[13];
    const float* Wn1 = (const float*)d_in[14];
    const float* bn1 = (const float*)d_in[15];
    const float* Wn2 = (const float*)d_in[16];
    const float* bn2 = (const float*)d_in[17];
    const float* alpha = (const float*)d_in[18];
    const float* beta  = (const float*)d_in[19];
    float* out = (float*)d_out;

    grid_bbox_kernel<<<NB, 256>>>(z);
    grid_count_kernel<<<NB * NPTS / 256, 256>>>(z);
    grid_scan_kernel<<<NB, 1024>>>();
    grid_scatter_kernel<<<NB * NPTS / 256, 256>>>(z);
    knn_query_kernel<<<NB * NPTS / 128, 128>>>();

    setup_kernel<<<1, 256>>>(t, cond, Wc1, bc1, Wc2, bc2, Wc3, bc3,
                             We1, be1, Wn1, bn1);

    int total_warps = NB * NPTS;
    int blocks = total_warps / 8;
    main_kernel<<<blocks, 256>>>(z, We1, We2, be2, Wn1, Wn2, bn2,
                                 alpha, beta, out);
}